// round 1
// baseline (speedup 1.0000x reference)
#include <cuda_runtime.h>
#include <cuda_bf16.h>
#include <cstddef>

// Problem constants (fixed by the reference setup_inputs)
#define BATCH   2
#define CHANS   256
#define IMG_H   200
#define IMG_W   200
#define HWSZ    (IMG_H * IMG_W)          // 40000
#define POOLED  7
#define NBIN    (POOLED * POOLED)        // 49
#define NSAMP   14                       // POOLED * S per axis
#define C4TOT   (CHANS / 4)              // 64 float4 groups
#define C4HALF  32                       // float4 groups per half-block

// 81.92 MB NHWC scratch: xt[b][h][w][c], viewed as float4 over channels.
__device__ float4 g_xt4[(size_t)BATCH * HWSZ * C4TOT];

// ---------------------------------------------------------------------------
// Kernel 1: NCHW -> NHWC transpose. x viewed as [B][C][HW] -> xt [B][HW][C].
// Tiled 32x32 via shared memory; fully coalesced on both sides.
// ---------------------------------------------------------------------------
__global__ __launch_bounds__(256) void nchw_to_nhwc(const float* __restrict__ x) {
    __shared__ float tile[32][33];
    const int b   = blockIdx.z;
    const int hw0 = blockIdx.x * 32;   // HW = 40000, divisible by 32
    const int c0  = blockIdx.y * 32;   // C = 256, divisible by 32
    const int tx  = threadIdx.x;
    const int ty  = threadIdx.y;       // blockDim = (32, 8)

    const float* xin = x + (size_t)b * CHANS * HWSZ;
    float*       xo  = (float*)g_xt4 + (size_t)b * HWSZ * CHANS;

#pragma unroll
    for (int i = 0; i < 32; i += 8)
        tile[ty + i][tx] = xin[(size_t)(c0 + ty + i) * HWSZ + hw0 + tx];
    __syncthreads();
#pragma unroll
    for (int i = 0; i < 32; i += 8)
        xo[(size_t)(hw0 + ty + i) * CHANS + c0 + tx] = tile[tx][ty + i];
}

// ---------------------------------------------------------------------------
// Kernel 2: RoIAlign gather. One block per (roi, channel-half).
//   - threads 0..27 build the per-axis sample tables (coords/weights) in smem,
//     exactly mirroring the reference _axis() clamping so all indices are
//     in [0, 199] and validity is folded into the weights.
//   - 8 sub-groups of 32 lanes; lane = float4 channel group; sub-group strides
//     over the 49 bins. Each bin: 2x2 samples x 4 corners = 16 coalesced
//     float4 gathers (512B per warp per load).
//   - results staged in smem [128 ch][49 bins], flushed with coalesced float4.
// ---------------------------------------------------------------------------
__global__ __launch_bounds__(256) void roi_gather(const float* __restrict__ rois,
                                                  float* __restrict__ out) {
    const int k    = blockIdx.x >> 1;
    const int half = blockIdx.x & 1;
    const int tid  = threadIdx.x;

    // tables: entries [0..13] = y axis (row offsets, float4 units),
    //         entries [14..27] = x axis (col offsets, float4 units)
    __shared__ float s_w0[28], s_w1[28];
    __shared__ int   s_lo[28], s_hi[28];
    __shared__ int   s_base;
    __shared__ float4 outs4[C4HALF * 4 * NBIN / 4];   // 128*49 floats = 25088 B
    float* outs = (float*)outs4;

    if (tid < 28) {
        const int isx = (tid >= 14);                  // 0 = y axis, 1 = x axis
        const int i   = isx ? tid - 14 : tid;         // sample index 0..13
        // y axis: rois cols 2 (start) / 4 (end);  x axis: cols 1 / 3
        const float r_s = rois[k * 5 + (isx ? 1 : 2)];
        const float r_e = rois[k * 5 + (isx ? 3 : 4)];
        const float start = r_s * 0.25f - 0.5f;
        const float end   = r_e * 0.25f - 0.5f;
        const float binsz = (end - start) * (1.0f / (float)POOLED);
        const int p = i >> 1, s = i & 1;
        float coord = start + ((float)p + ((float)s + 0.5f) * 0.5f) * binsz;
        const float limit = 200.0f;                   // H == W == 200
        const float valid = (coord >= -1.0f && coord <= limit) ? 1.0f : 0.0f;
        float c = fmaxf(coord, 0.0f);
        int lo0 = (int)floorf(c);
        const bool cap = (lo0 >= IMG_H - 1);
        const int lo = cap ? IMG_H - 1 : lo0;
        const int hi = cap ? IMG_H - 1 : lo0 + 1;
        if (cap) c = (float)lo;
        const float l = c - (float)lo;
        s_w0[tid] = (1.0f - l) * valid;
        s_w1[tid] = l * valid;
        const int mul = isx ? C4TOT : IMG_W * C4TOT;  // col vs row stride (float4 units)
        s_lo[tid] = lo * mul;
        s_hi[tid] = hi * mul;
    }
    if (tid == 28) {
        s_base = (int)rois[k * 5] * (HWSZ * C4TOT);   // batch base, float4 units
    }
    __syncthreads();

    const int lane = tid & 31;                        // float4 group within half
    const int sub  = tid >> 5;                        // 0..7
    const int base = s_base + (half << 5) + lane;     // c4 = half*32 + lane
    const float4* __restrict__ xt4 = g_xt4;

    for (int bin = sub; bin < NBIN; bin += 8) {
        const int ph = bin / POOLED;
        const int pw = bin - ph * POOLED;
        float4 acc = make_float4(0.f, 0.f, 0.f, 0.f);
#pragma unroll
        for (int sy = 0; sy < 2; ++sy) {
            const int iy   = ph * 2 + sy;
            const int ylo  = s_lo[iy], yhi = s_hi[iy];
            const float wy0 = s_w0[iy], wy1 = s_w1[iy];
#pragma unroll
            for (int sx = 0; sx < 2; ++sx) {
                const int ix   = 14 + pw * 2 + sx;
                const int xlo  = s_lo[ix], xhi = s_hi[ix];
                const float wx0 = s_w0[ix], wx1 = s_w1[ix];
                const float4 v00 = xt4[base + ylo + xlo];
                const float4 v01 = xt4[base + ylo + xhi];
                const float4 v10 = xt4[base + yhi + xlo];
                const float4 v11 = xt4[base + yhi + xhi];
                const float w00 = wy0 * wx0, w01 = wy0 * wx1;
                const float w10 = wy1 * wx0, w11 = wy1 * wx1;
                acc.x += w00 * v00.x + w01 * v01.x + w10 * v10.x + w11 * v11.x;
                acc.y += w00 * v00.y + w01 * v01.y + w10 * v10.y + w11 * v11.y;
                acc.z += w00 * v00.z + w01 * v01.z + w10 * v10.z + w11 * v11.z;
                acc.w += w00 * v00.w + w01 * v01.w + w10 * v10.w + w11 * v11.w;
            }
        }
        // local channel = lane*4 + j ; smem layout [channel][bin] == global order
        float* o = outs + (lane * 4) * NBIN + bin;
        o[0 * NBIN] = acc.x * 0.25f;
        o[1 * NBIN] = acc.y * 0.25f;
        o[2 * NBIN] = acc.z * 0.25f;
        o[3 * NBIN] = acc.w * 0.25f;
    }
    __syncthreads();

    // coalesced flush: 128*49 = 6272 floats = 1568 float4, contiguous in out
    float4* og = (float4*)out + (size_t)k * (CHANS * NBIN / 4) + half * 1568;
#pragma unroll 2
    for (int i = tid; i < 1568; i += 256)
        og[i] = outs4[i];
}

extern "C" void kernel_launch(void* const* d_in, const int* in_sizes, int n_in,
                              void* d_out, int out_size) {
    const float* x    = (const float*)d_in[0];
    const float* rois = (const float*)d_in[1];
    float* out        = (float*)d_out;
    const int K = in_sizes[1] / 5;

    dim3 tgrid(HWSZ / 32, CHANS / 32, BATCH);   // 1250 x 8 x 2
    nchw_to_nhwc<<<tgrid, dim3(32, 8)>>>(x);
    roi_gather<<<2 * K, 256>>>(rois, out);
}